// round 1
// baseline (speedup 1.0000x reference)
#include <cuda_runtime.h>
#include <cuda_bf16.h>
#include <math.h>

// ---------------------------------------------------------------------------
// Problem constants
//   hidden_states: [2,1,1024,4544] f32   -> X [2048, 4544]
//   attention_mask: [2,1,1024,1024] f32  (pure causal; recomputed in-kernel)
//   qkv_w: [4544, 4672] f32              (4672 = 73*64: 71 Q heads, 1 K, 1 V)
//   dense_w: [4544, 4544] f32
//   out: [2,1,1024,4544] f32             -> [2048, 4544]
// ---------------------------------------------------------------------------

#define HID   4544
#define QKVN  4672          // 73*64
#define NHEAD 71
#define HD    64
#define SEQ   1024
#define ROWS  2048          // b*s

// Scratch (device globals; no allocation allowed)
__device__ float g_qkv[(size_t)ROWS * QKVN];   // fused qkv after GEMM (+RoPE in place)
__device__ float g_ctx[(size_t)ROWS * HID];    // attention output, [b*s, head*64+d]
__device__ float g_cos[SEQ * 32];
__device__ float g_sin[SEQ * 32];

// ---------------------------------------------------------------------------
// SGEMM: C[M,N] = A[M,K] * B[K,N], row-major, fp32.
// 128x128 block tile, BK=16, 256 threads, 8x8 per-thread micro-tile,
// double-buffered shared memory. Requires M%128==0, K%16==0, N%8==0.
// ---------------------------------------------------------------------------
__global__ __launch_bounds__(256, 2)
void sgemm128(const float* __restrict__ A, const float* __restrict__ B,
              float* __restrict__ C, int M, int N, int K)
{
    __shared__ float As[2][16][128];   // transposed: As[k][m]
    __shared__ float Bs[2][16][128];   // Bs[k][n]

    const int tid  = threadIdx.x;
    const int row0 = blockIdx.y * 128;
    const int col0 = blockIdx.x * 128;

    // global-load mapping
    const int ar = tid >> 2;            // 0..63 (A row; also +64)
    const int ac = (tid & 3) * 4;       // 0,4,8,12 (A k-offset)
    const int br = tid >> 5;            // 0..7  (B k-row; also +8)
    const int bc = (tid & 31) * 4;      // 0..124 (B col)

    // compute mapping
    const int tx = tid & 15, ty = tid >> 4;
    const int trow = ty * 8, tcol = tx * 8;

    float acc[8][8];
#pragma unroll
    for (int i = 0; i < 8; i++)
#pragma unroll
        for (int j = 0; j < 8; j++) acc[i][j] = 0.f;

    const int nk = K >> 4;
    const bool bok = (col0 + bc) < N;

    float4 a0, a1, b0, b1;
    // prologue: tile 0 -> buffer 0
    {
        const float* Ap = A + (size_t)(row0 + ar) * K + ac;
        a0 = *(const float4*)Ap;
        a1 = *(const float4*)(Ap + (size_t)64 * K);
        if (bok) {
            const float* Bp = B + (size_t)br * N + col0 + bc;
            b0 = *(const float4*)Bp;
            b1 = *(const float4*)(Bp + (size_t)8 * N);
        } else { b0 = make_float4(0,0,0,0); b1 = b0; }
        As[0][ac+0][ar] = a0.x; As[0][ac+1][ar] = a0.y;
        As[0][ac+2][ar] = a0.z; As[0][ac+3][ar] = a0.w;
        As[0][ac+0][ar+64] = a1.x; As[0][ac+1][ar+64] = a1.y;
        As[0][ac+2][ar+64] = a1.z; As[0][ac+3][ar+64] = a1.w;
        *(float4*)&Bs[0][br][bc]   = b0;
        *(float4*)&Bs[0][br+8][bc] = b1;
    }
    __syncthreads();

    for (int kt = 0; kt < nk; ++kt) {
        const int cur = kt & 1;
        const bool more = (kt + 1) < nk;
        if (more) {
            const int k0 = (kt + 1) << 4;
            const float* Ap = A + (size_t)(row0 + ar) * K + k0 + ac;
            a0 = *(const float4*)Ap;
            a1 = *(const float4*)(Ap + (size_t)64 * K);
            if (bok) {
                const float* Bp = B + (size_t)(k0 + br) * N + col0 + bc;
                b0 = *(const float4*)Bp;
                b1 = *(const float4*)(Bp + (size_t)8 * N);
            } else { b0 = make_float4(0,0,0,0); b1 = b0; }
        }
#pragma unroll
        for (int k = 0; k < 16; ++k) {
            float4 fa0 = *(const float4*)&As[cur][k][trow];
            float4 fa1 = *(const float4*)&As[cur][k][trow + 4];
            float4 fb0 = *(const float4*)&Bs[cur][k][tcol];
            float4 fb1 = *(const float4*)&Bs[cur][k][tcol + 4];
            float av[8] = {fa0.x, fa0.y, fa0.z, fa0.w, fa1.x, fa1.y, fa1.z, fa1.w};
            float bv[8] = {fb0.x, fb0.y, fb0.z, fb0.w, fb1.x, fb1.y, fb1.z, fb1.w};
#pragma unroll
            for (int i = 0; i < 8; i++)
#pragma unroll
                for (int j = 0; j < 8; j++)
                    acc[i][j] += av[i] * bv[j];
        }
        if (more) {
            const int nb = (kt + 1) & 1;
            As[nb][ac+0][ar] = a0.x; As[nb][ac+1][ar] = a0.y;
            As[nb][ac+2][ar] = a0.z; As[nb][ac+3][ar] = a0.w;
            As[nb][ac+0][ar+64] = a1.x; As[nb][ac+1][ar+64] = a1.y;
            As[nb][ac+2][ar+64] = a1.z; As[nb][ac+3][ar+64] = a1.w;
            *(float4*)&Bs[nb][br][bc]   = b0;
            *(float4*)&Bs[nb][br+8][bc] = b1;
        }
        __syncthreads();
    }

    if ((col0 + tcol) < N) {
#pragma unroll
        for (int i = 0; i < 8; ++i) {
            float* Cp = C + (size_t)(row0 + trow + i) * N + col0 + tcol;
            *(float4*)Cp       = make_float4(acc[i][0], acc[i][1], acc[i][2], acc[i][3]);
            *(float4*)(Cp + 4) = make_float4(acc[i][4], acc[i][5], acc[i][6], acc[i][7]);
        }
    }
}

// ---------------------------------------------------------------------------
// RoPE tables: cos/sin[pos][i], i=0..31. inv_freq computed in double to match
// the fp32 reference to <1 ulp of angle.
// ---------------------------------------------------------------------------
__global__ void rope_table_kernel()
{
    int idx = blockIdx.x * blockDim.x + threadIdx.x;
    if (idx >= SEQ * 32) return;
    int pos = idx >> 5, i = idx & 31;
    double inv = exp(-((double)(2 * i) / 64.0) * log(10000.0));
    float ang = (float)pos * (float)inv;
    g_cos[idx] = cosf(ang);
    g_sin[idx] = sinf(ang);
}

// ---------------------------------------------------------------------------
// RoPE applied in-place to heads 0..70 (Q) and 71 (K) of g_qkv.
// out[j]    = x[j]*cos - x[j+32]*sin
// out[j+32] = x[j+32]*cos + x[j]*sin        (cos/sin indexed by j%32)
// ---------------------------------------------------------------------------
__global__ __launch_bounds__(256)
void rope_kernel(float* __restrict__ qkv)
{
    const int row = blockIdx.x;            // 0..2047
    const int pos = row & (SEQ - 1);
    float* base = qkv + (size_t)row * QKVN;
    for (int idx = threadIdx.x; idx < 72 * 32; idx += blockDim.x) {
        int h = idx >> 5, i = idx & 31;
        float c = g_cos[pos * 32 + i];
        float s = g_sin[pos * 32 + i];
        float* p = base + h * 64;
        float x1 = p[i], x2 = p[i + 32];
        p[i]      = x1 * c - x2 * s;
        p[i + 32] = x2 * c + x1 * s;
    }
}

// ---------------------------------------------------------------------------
// Flash-style causal MQA attention, fp32.
// Grid: (16 q-tiles, 71 heads, 2 batch). Block: 128 threads.
// Per block: Q tile [64,64] resident in smem; loop over k-tiles <= q-tile,
// online softmax; K smem buffer reused for P. ctx written as [row, h*64+d].
// Thread map: tx=tid&15 (16 lanes), ty=tid>>4 (8 groups of 8 rows).
//   S cols  j = tx + 16*jj (jj 0..3)    O cols d = tx + 16*dd (dd 0..3)
// ---------------------------------------------------------------------------
#define QP 65   // pitch for Qs / KPs (odd -> conflict-free column-ish access)
#define VP 64   // pitch for Vs (stride-1 access across tx)

__global__ __launch_bounds__(128)
void attn_kernel(const float* __restrict__ qkv, float* __restrict__ ctx)
{
    extern __shared__ float sm[];
    float* Qs  = sm;                 // [64][QP]
    float* KPs = sm + 64 * QP;       // [64][QP]  (K tile, then reused for P)
    float* Vs  = sm + 2 * 64 * QP;   // [64][VP]

    const int qt = blockIdx.x, h = blockIdx.y, b = blockIdx.z;
    const int tid = threadIdx.x;
    const int tx = tid & 15, ty = tid >> 4;
    const size_t ld = QKVN;

    const float* qbase = qkv + ((size_t)(b * SEQ + qt * 64)) * ld + h * 64;
    const float* kbase = qkv + ((size_t)(b * SEQ)) * ld + NHEAD * 64;       // col 4544
    const float* vbase = qkv + ((size_t)(b * SEQ)) * ld + (NHEAD + 1) * 64; // col 4608

    // load Q tile
    for (int idx = tid; idx < 64 * 16; idx += 128) {
        int r = idx >> 4, c4 = (idx & 15) * 4;
        float4 v = *(const float4*)(qbase + (size_t)r * ld + c4);
        float* d = Qs + r * QP + c4;
        d[0] = v.x; d[1] = v.y; d[2] = v.z; d[3] = v.w;
    }

    float m[8], l[8], acc[8][4];
#pragma unroll
    for (int i = 0; i < 8; i++) {
        m[i] = -1e30f; l[i] = 0.f;
#pragma unroll
        for (int d = 0; d < 4; d++) acc[i][d] = 0.f;
    }

    const float scale = 0.125f;  // 1/sqrt(64)

    for (int kt = 0; kt <= qt; ++kt) {
        __syncthreads();  // prior P reads done (and Q visible on first iter)

        // load K,V tiles
        for (int idx = tid; idx < 64 * 16; idx += 128) {
            int r = idx >> 4, c4 = (idx & 15) * 4;
            float4 kv4 = *(const float4*)(kbase + (size_t)(kt * 64 + r) * ld + c4);
            float4 vv4 = *(const float4*)(vbase + (size_t)(kt * 64 + r) * ld + c4);
            float* kd = KPs + r * QP + c4;
            kd[0] = kv4.x; kd[1] = kv4.y; kd[2] = kv4.z; kd[3] = kv4.w;
            *(float4*)(Vs + r * VP + c4) = vv4;
        }
        __syncthreads();

        // S = Q @ K^T
        float s[8][4];
#pragma unroll
        for (int i = 0; i < 8; i++) { s[i][0]=0.f; s[i][1]=0.f; s[i][2]=0.f; s[i][3]=0.f; }
#pragma unroll 8
        for (int d0 = 0; d0 < 64; ++d0) {
            float kf[4];
#pragma unroll
            for (int jj = 0; jj < 4; jj++) kf[jj] = KPs[(tx + jj * 16) * QP + d0];
#pragma unroll
            for (int ii = 0; ii < 8; ii++) {
                float qv = Qs[(ty * 8 + ii) * QP + d0];
                s[ii][0] += qv * kf[0];
                s[ii][1] += qv * kf[1];
                s[ii][2] += qv * kf[2];
                s[ii][3] += qv * kf[3];
            }
        }

        // scale + causal mask + online softmax update
        const bool diag = (kt == qt);
#pragma unroll
        for (int ii = 0; ii < 8; ii++) {
            const int gi = ty * 8 + ii;
            float rmax = -1e30f;
#pragma unroll
            for (int jj = 0; jj < 4; jj++) {
                float v = s[ii][jj] * scale;
                if (diag && (tx + jj * 16) > gi) v = -1e30f;
                s[ii][jj] = v;
                rmax = fmaxf(rmax, v);
            }
#pragma unroll
            for (int off = 1; off < 16; off <<= 1)
                rmax = fmaxf(rmax, __shfl_xor_sync(0xffffffffu, rmax, off));
            float mnew = fmaxf(m[ii], rmax);
            float corr = __expf(m[ii] - mnew);
            m[ii] = mnew;
            float rsum = 0.f;
#pragma unroll
            for (int jj = 0; jj < 4; jj++) {
                float p = __expf(s[ii][jj] - mnew);
                s[ii][jj] = p;
                rsum += p;
            }
#pragma unroll
            for (int off = 1; off < 16; off <<= 1)
                rsum += __shfl_xor_sync(0xffffffffu, rsum, off);
            l[ii] = l[ii] * corr + rsum;
#pragma unroll
            for (int dd = 0; dd < 4; dd++) acc[ii][dd] *= corr;
        }
        __syncthreads();   // all K reads done -> reuse KPs for P

        // write P
#pragma unroll
        for (int ii = 0; ii < 8; ii++)
#pragma unroll
            for (int jj = 0; jj < 4; jj++)
                KPs[(ty * 8 + ii) * QP + tx + jj * 16] = s[ii][jj];
        __syncthreads();

        // O += P @ V
#pragma unroll 8
        for (int j = 0; j < 64; ++j) {
            float vf[4];
#pragma unroll
            for (int dd = 0; dd < 4; dd++) vf[dd] = Vs[j * VP + tx + dd * 16];
#pragma unroll
            for (int ii = 0; ii < 8; ii++) {
                float pv = KPs[(ty * 8 + ii) * QP + j];
                acc[ii][0] += pv * vf[0];
                acc[ii][1] += pv * vf[1];
                acc[ii][2] += pv * vf[2];
                acc[ii][3] += pv * vf[3];
            }
        }
    }

    // epilogue: O / l -> ctx[row, h*64 + d]
#pragma unroll
    for (int ii = 0; ii < 8; ii++) {
        float inv = 1.0f / l[ii];
        int row = b * SEQ + qt * 64 + ty * 8 + ii;
        float* o = ctx + (size_t)row * HID + h * 64;
#pragma unroll
        for (int dd = 0; dd < 4; dd++)
            o[tx + dd * 16] = acc[ii][dd] * inv;
    }
}

// ---------------------------------------------------------------------------
// kernel_launch
// Inputs (metadata order): hidden_states, attention_mask(unused; pure causal),
// qkv_w, dense_w. Output: [2048, 4544] f32.
// ---------------------------------------------------------------------------
extern "C" void kernel_launch(void* const* d_in, const int* in_sizes, int n_in,
                              void* d_out, int out_size)
{
    const float* hidden  = (const float*)d_in[0];
    const float* qkv_w   = (const float*)d_in[2];
    const float* dense_w = (const float*)d_in[3];
    float* out = (float*)d_out;

    float* qkv; cudaGetSymbolAddress((void**)&qkv, g_qkv);
    float* ctx; cudaGetSymbolAddress((void**)&ctx, g_ctx);

    const int attn_smem = (2 * 64 * QP + 64 * VP) * (int)sizeof(float); // 49664
    cudaFuncSetAttribute(attn_kernel, cudaFuncAttributeMaxDynamicSharedMemorySize,
                         attn_smem);

    // 1) QKV GEMM: [2048,4544] x [4544,4672]
    {
        dim3 grid((QKVN + 127) / 128, ROWS / 128);
        sgemm128<<<grid, 256>>>(hidden, qkv_w, qkv, ROWS, QKVN, HID);
    }
    // 2) RoPE tables + in-place RoPE on Q heads and K head
    rope_table_kernel<<<(SEQ * 32 + 255) / 256, 256>>>();
    rope_kernel<<<ROWS, 256>>>(qkv);
    // 3) Attention -> ctx
    {
        dim3 grid(SEQ / 64, NHEAD, 2);
        attn_kernel<<<grid, 128, attn_smem>>>(qkv, ctx);
    }
    // 4) Dense GEMM: [2048,4544] x [4544,4544] -> out
    {
        dim3 grid((HID + 127) / 128, ROWS / 128);
        sgemm128<<<grid, 256>>>(ctx, dense_w, out, ROWS, HID, HID);
    }
}

// round 5
// speedup vs baseline: 2.0215x; 2.0215x over previous
#include <cuda_runtime.h>
#include <cuda_bf16.h>
#include <math.h>
#include <stdint.h>

// ---------------------------------------------------------------------------
// Falcon MQA attention block, fp32 in/out.
//   X [2048,4544] @ qkv_w [4544,4672] -> RoPE -> 71-head MQA causal attn
//   -> ctx [2048,4544] @ dense_w [4544,4544] -> out
// GEMMs: warp-level bf16 tensor-core mma.sync (m16n8k16) with split-bf16
// (hi+lo): C = Ah*Bh + Ah*Bl + Al*Bh, fp32 accumulation.
// (tcgen05 unavailable: harness compiles for base sm_100, not sm_100a.)
// ---------------------------------------------------------------------------

#define HID   4544
#define QKVN  4672           // 73*64
#define QKVP  4736           // padded to 37*128
#define DNP   4608           // dense N padded to 36*128
#define NHEAD 71
#define SEQ   1024
#define ROWS  2048
#define GK    4544           // GEMM K

// Scratch (device globals; no allocation allowed)
__device__ float g_qkv[(size_t)ROWS * QKVP];
__device__ float g_ctx[(size_t)ROWS * HID];
__device__ float g_cos[SEQ * 32];
__device__ float g_sin[SEQ * 32];
__device__ __nv_bfloat16 g_ah[(size_t)ROWS * HID];   // activation hi split
__device__ __nv_bfloat16 g_al[(size_t)ROWS * HID];   // activation lo split
__device__ __nv_bfloat16 g_wth[(size_t)QKVP * HID];  // weight^T hi  [Npad][K]
__device__ __nv_bfloat16 g_wtl[(size_t)QKVP * HID];  // weight^T lo

// ---------------------------------------------------------------------------
// PTX helpers
// ---------------------------------------------------------------------------
__device__ __forceinline__ uint32_t smem_u32(const void* p) {
    uint32_t a;
    asm("{ .reg .u64 t; cvta.to.shared.u64 t, %1; cvt.u32.u64 %0, t; }"
        : "=r"(a) : "l"(p));
    return a;
}
__device__ __forceinline__ void ldm4(uint32_t* r, uint32_t addr) {
    asm volatile("ldmatrix.sync.aligned.m8n8.x4.shared.b16 {%0,%1,%2,%3}, [%4];"
                 : "=r"(r[0]), "=r"(r[1]), "=r"(r[2]), "=r"(r[3]) : "r"(addr));
}
__device__ __forceinline__ void mma16816(float* d, const uint32_t* a, const uint32_t* b) {
    asm volatile(
        "mma.sync.aligned.m16n8k16.row.col.f32.bf16.bf16.f32 "
        "{%0,%1,%2,%3}, {%4,%5,%6,%7}, {%8,%9}, {%0,%1,%2,%3};"
        : "+f"(d[0]), "+f"(d[1]), "+f"(d[2]), "+f"(d[3])
        : "r"(a[0]), "r"(a[1]), "r"(a[2]), "r"(a[3]), "r"(b[0]), "r"(b[1]));
}
#define CP16(dst, src) \
    asm volatile("cp.async.cg.shared.global [%0], [%1], 16;" :: "r"(dst), "l"(src))
#define CP_COMMIT() asm volatile("cp.async.commit_group;" ::: "memory")
#define CP_WAIT1()  asm volatile("cp.async.wait_group 1;" ::: "memory")

// ---------------------------------------------------------------------------
// Elementwise split: x -> bf16 hi + bf16 lo
// ---------------------------------------------------------------------------
__global__ __launch_bounds__(256)
void split_act(const float* __restrict__ x, __nv_bfloat16* __restrict__ h,
               __nv_bfloat16* __restrict__ l, int n)
{
    int i = (blockIdx.x * blockDim.x + threadIdx.x) * 4;
    if (i + 3 >= n) {
        for (; i < n; ++i) {
            float v = x[i];
            __nv_bfloat16 hb = __float2bfloat16(v);
            h[i] = hb; l[i] = __float2bfloat16(v - __bfloat162float(hb));
        }
        return;
    }
    float4 v = *(const float4*)(x + i);
    __nv_bfloat16 h0 = __float2bfloat16(v.x), h1 = __float2bfloat16(v.y);
    __nv_bfloat16 h2 = __float2bfloat16(v.z), h3 = __float2bfloat16(v.w);
    __nv_bfloat162 hp0 = {h0, h1}, hp1 = {h2, h3};
    __nv_bfloat162 lp0 = {__float2bfloat16(v.x - __bfloat162float(h0)),
                          __float2bfloat16(v.y - __bfloat162float(h1))};
    __nv_bfloat162 lp1 = {__float2bfloat16(v.z - __bfloat162float(h2)),
                          __float2bfloat16(v.w - __bfloat162float(h3))};
    *(__nv_bfloat162*)(h + i)     = hp0;
    *(__nv_bfloat162*)(h + i + 2) = hp1;
    *(__nv_bfloat162*)(l + i)     = lp0;
    *(__nv_bfloat162*)(l + i + 2) = lp1;
}

// ---------------------------------------------------------------------------
// Weight transpose + split: W [K,N] f32 -> Th/Tl [Npad,K] bf16 (zero-padded)
// ---------------------------------------------------------------------------
__global__ __launch_bounds__(256)
void transpose_split(const float* __restrict__ W, __nv_bfloat16* __restrict__ Th,
                     __nv_bfloat16* __restrict__ Tl, int K, int N)
{
    __shared__ float t[32][33];
    const int n0 = blockIdx.x * 32, k0 = blockIdx.y * 32;
    const int tx = threadIdx.x, ty = threadIdx.y;
#pragma unroll
    for (int i = 0; i < 4; ++i) {
        int k = k0 + ty + i * 8, n = n0 + tx;
        t[ty + i * 8][tx] = (n < N) ? W[(size_t)k * N + n] : 0.f;
    }
    __syncthreads();
#pragma unroll
    for (int i = 0; i < 4; ++i) {
        int n = n0 + ty + i * 8, k = k0 + tx;
        float v = t[tx][ty + i * 8];
        __nv_bfloat16 hb = __float2bfloat16(v);
        Th[(size_t)n * K + k] = hb;
        Tl[(size_t)n * K + k] = __float2bfloat16(v - __bfloat162float(hb));
    }
}

// ---------------------------------------------------------------------------
// HMMA split-bf16 GEMM.
// C[M,N] = (Ah+Al)[M,K] * (Bh+Bl)^T[N,K], fp32 accumulate (Al*Bl dropped).
// CTA tile 128x128, BK=32, 256 threads (8 warps, 2x4; 64x32 per warp).
// Smem: 2 stages x {Ah,Al,Bh,Bl} tiles of [128 rows x 32 bf16], row pitch
// 80 B (conflict-free ldmatrix). cp.async double-buffer pipeline.
// ---------------------------------------------------------------------------
#define PITCH  80
#define TILEB  (128 * PITCH)    // 10240
#define STAGEB (4 * TILEB)      // 40960
#define GSMEM  (2 * STAGEB)     // 81920
#define NCHUNK (GK / 32)        // 142

__device__ __forceinline__ void load_chunk(
    uint32_t smb, int stage,
    const __nv_bfloat16* __restrict__ Ah, const __nv_bfloat16* __restrict__ Al,
    const __nv_bfloat16* __restrict__ Bh, const __nv_bfloat16* __restrict__ Bl,
    int m0, int n0, int k0, int tid)
{
    uint32_t sb = smb + stage * STAGEB;
#pragma unroll
    for (int it = 0; it < 2; ++it) {
        int idx = tid + it * 256;          // 0..511
        int row = idx >> 2, c16 = idx & 3;
        uint32_t doff = (uint32_t)(row * PITCH + c16 * 16);
        size_t aoff = (size_t)(m0 + row) * GK + k0 + c16 * 8;
        size_t boff = (size_t)(n0 + row) * GK + k0 + c16 * 8;
        CP16(sb + 0 * TILEB + doff, Ah + aoff);
        CP16(sb + 1 * TILEB + doff, Al + aoff);
        CP16(sb + 2 * TILEB + doff, Bh + boff);
        CP16(sb + 3 * TILEB + doff, Bl + boff);
    }
}

__global__ __launch_bounds__(256, 1)
void gemm_hmma(const __nv_bfloat16* __restrict__ Ah,
               const __nv_bfloat16* __restrict__ Al,
               const __nv_bfloat16* __restrict__ Bh,
               const __nv_bfloat16* __restrict__ Bl,
               float* __restrict__ C, int Nstride, int Nlimit)
{
    extern __shared__ char sm[];
    const uint32_t smb = smem_u32(sm);
    const int tid = threadIdx.x;
    const int wid = tid >> 5, lane = tid & 31;
    const int m0 = blockIdx.y * 128, n0 = blockIdx.x * 128;
    const int wm = wid >> 2, wn = wid & 3;         // warp 2x4 -> 64x32

    // lane-constant ldmatrix offsets (bytes)
    const int ra = lane & 15;                       // A row within 16
    const int ca = (lane >> 4) * 8;                 // A col sel (bf16 units)
    const uint32_t aoff = (uint32_t)((wm * 64 + ra) * PITCH + ca * 2);
    const int rb = ((lane >> 4) * 8) + (lane & 7);  // B row within 16
    const int cb = ((lane >> 3) & 1) * 8;           // B col sel
    const uint32_t boff = (uint32_t)((wn * 32 + rb) * PITCH + cb * 2);

    float acc[4][4][4];
#pragma unroll
    for (int i = 0; i < 4; i++)
#pragma unroll
        for (int j = 0; j < 4; j++)
#pragma unroll
            for (int k = 0; k < 4; k++) acc[i][j][k] = 0.f;

    load_chunk(smb, 0, Ah, Al, Bh, Bl, m0, n0, 0, tid);
    CP_COMMIT();

    for (int c = 0; c < NCHUNK; ++c) {
        if (c + 1 < NCHUNK)
            load_chunk(smb, (c + 1) & 1, Ah, Al, Bh, Bl, m0, n0, (c + 1) * 32, tid);
        CP_COMMIT();
        CP_WAIT1();
        __syncthreads();

        const uint32_t sb = smb + (c & 1) * STAGEB;
#pragma unroll
        for (int ks = 0; ks < 2; ++ks) {
            const uint32_t koff = (uint32_t)(ks * 32);   // 16 bf16 = 32 B
            uint32_t aH[4][4], aL[4][4], bH[4][2], bL[4][2];
#pragma unroll
            for (int mt = 0; mt < 4; ++mt) {
                ldm4(aH[mt], sb + 0 * TILEB + aoff + mt * 16 * PITCH + koff);
                ldm4(aL[mt], sb + 1 * TILEB + aoff + mt * 16 * PITCH + koff);
            }
#pragma unroll
            for (int p = 0; p < 2; ++p) {
                uint32_t r[4];
                ldm4(r, sb + 2 * TILEB + boff + p * 16 * PITCH + koff);
                bH[2 * p][0] = r[0]; bH[2 * p][1] = r[1];
                bH[2 * p + 1][0] = r[2]; bH[2 * p + 1][1] = r[3];
                ldm4(r, sb + 3 * TILEB + boff + p * 16 * PITCH + koff);
                bL[2 * p][0] = r[0]; bL[2 * p][1] = r[1];
                bL[2 * p + 1][0] = r[2]; bL[2 * p + 1][1] = r[3];
            }
#pragma unroll
            for (int mt = 0; mt < 4; ++mt)
#pragma unroll
                for (int nt = 0; nt < 4; ++nt) {
                    mma16816(acc[mt][nt], aH[mt], bH[nt]);
                    mma16816(acc[mt][nt], aH[mt], bL[nt]);
                    mma16816(acc[mt][nt], aL[mt], bH[nt]);
                }
        }
        __syncthreads();
    }

    // epilogue: lane holds rows (r, r+8), cols (c, c+1) per tile
    const int rbase = m0 + wm * 64 + (lane >> 2);
    const int cbase = n0 + wn * 32 + (lane & 3) * 2;
#pragma unroll
    for (int mt = 0; mt < 4; ++mt) {
#pragma unroll
        for (int nt = 0; nt < 4; ++nt) {
            const int col = cbase + nt * 8;
            if (col < Nlimit) {
                const int r = rbase + mt * 16;
                float* p0 = C + (size_t)r * Nstride + col;
                float* p1 = C + (size_t)(r + 8) * Nstride + col;
                *(float2*)p0 = make_float2(acc[mt][nt][0], acc[mt][nt][1]);
                *(float2*)p1 = make_float2(acc[mt][nt][2], acc[mt][nt][3]);
            }
        }
    }
}

// ---------------------------------------------------------------------------
// RoPE tables + in-place RoPE (stride QKVP)
// ---------------------------------------------------------------------------
__global__ void rope_table_kernel()
{
    int idx = blockIdx.x * blockDim.x + threadIdx.x;
    if (idx >= SEQ * 32) return;
    int pos = idx >> 5, i = idx & 31;
    double inv = exp(-((double)(2 * i) / 64.0) * log(10000.0));
    float ang = (float)pos * (float)inv;
    g_cos[idx] = cosf(ang);
    g_sin[idx] = sinf(ang);
}

__global__ __launch_bounds__(256)
void rope_kernel(float* __restrict__ qkv)
{
    const int row = blockIdx.x;
    const int pos = row & (SEQ - 1);
    float* base = qkv + (size_t)row * QKVP;
    for (int idx = threadIdx.x; idx < 72 * 32; idx += blockDim.x) {
        int h = idx >> 5, i = idx & 31;
        float c = g_cos[pos * 32 + i];
        float s = g_sin[pos * 32 + i];
        float* p = base + h * 64;
        float x1 = p[i], x2 = p[i + 32];
        p[i]      = x1 * c - x2 * s;
        p[i + 32] = x2 * c + x1 * s;
    }
}

// ---------------------------------------------------------------------------
// Flash-style causal MQA attention, fp32.
// ---------------------------------------------------------------------------
#define QP 65
#define VP 64

__global__ __launch_bounds__(128)
void attn_kernel(const float* __restrict__ qkv, float* __restrict__ ctx)
{
    extern __shared__ float smf[];
    float* Qs  = smf;
    float* KPs = smf + 64 * QP;
    float* Vs  = smf + 2 * 64 * QP;

    const int qt = blockIdx.x, h = blockIdx.y, b = blockIdx.z;
    const int tid = threadIdx.x;
    const int tx = tid & 15, ty = tid >> 4;
    const size_t ld = QKVP;

    const float* qbase = qkv + ((size_t)(b * SEQ + qt * 64)) * ld + h * 64;
    const float* kbase = qkv + ((size_t)(b * SEQ)) * ld + NHEAD * 64;
    const float* vbase = qkv + ((size_t)(b * SEQ)) * ld + (NHEAD + 1) * 64;

    for (int idx = tid; idx < 64 * 16; idx += 128) {
        int r = idx >> 4, c4 = (idx & 15) * 4;
        float4 v = *(const float4*)(qbase + (size_t)r * ld + c4);
        float* d = Qs + r * QP + c4;
        d[0] = v.x; d[1] = v.y; d[2] = v.z; d[3] = v.w;
    }

    float m[8], l[8], acc[8][4];
#pragma unroll
    for (int i = 0; i < 8; i++) {
        m[i] = -1e30f; l[i] = 0.f;
#pragma unroll
        for (int d = 0; d < 4; d++) acc[i][d] = 0.f;
    }

    const float scale = 0.125f;

    for (int kt = 0; kt <= qt; ++kt) {
        __syncthreads();
        for (int idx = tid; idx < 64 * 16; idx += 128) {
            int r = idx >> 4, c4 = (idx & 15) * 4;
            float4 kv4 = *(const float4*)(kbase + (size_t)(kt * 64 + r) * ld + c4);
            float4 vv4 = *(const float4*)(vbase + (size_t)(kt * 64 + r) * ld + c4);
            float* kd = KPs + r * QP + c4;
            kd[0] = kv4.x; kd[1] = kv4.y; kd[2] = kv4.z; kd[3] = kv4.w;
            *(float4*)(Vs + r * VP + c4) = vv4;
        }
        __syncthreads();

        float s[8][4];
#pragma unroll
        for (int i = 0; i < 8; i++) { s[i][0]=0.f; s[i][1]=0.f; s[i][2]=0.f; s[i][3]=0.f; }
#pragma unroll 8
        for (int d0 = 0; d0 < 64; ++d0) {
            float kf[4];
#pragma unroll
            for (int jj = 0; jj < 4; jj++) kf[jj] = KPs[(tx + jj * 16) * QP + d0];
#pragma unroll
            for (int ii = 0; ii < 8; ii++) {
                float qv = Qs[(ty * 8 + ii) * QP + d0];
                s[ii][0] += qv * kf[0];
                s[ii][1] += qv * kf[1];
                s[ii][2] += qv * kf[2];
                s[ii][3] += qv * kf[3];
            }
        }

        const bool diag = (kt == qt);
#pragma unroll
        for (int ii = 0; ii < 8; ii++) {
            const int gi = ty * 8 + ii;
            float rmax = -1e30f;
#pragma unroll
            for (int jj = 0; jj < 4; jj++) {
                float v = s[ii][jj] * scale;
                if (diag && (tx + jj * 16) > gi) v = -1e30f;
                s[ii][jj] = v;
                rmax = fmaxf(rmax, v);
            }
#pragma unroll
            for (int off = 1; off < 16; off <<= 1)
                rmax = fmaxf(rmax, __shfl_xor_sync(0xffffffffu, rmax, off));
            float mnew = fmaxf(m[ii], rmax);
            float corr = __expf(m[ii] - mnew);
            m[ii] = mnew;
            float rsum = 0.f;
#pragma unroll
            for (int jj = 0; jj < 4; jj++) {
                float p = __expf(s[ii][jj] - mnew);
                s[ii][jj] = p;
                rsum += p;
            }
#pragma unroll
            for (int off = 1; off < 16; off <<= 1)
                rsum += __shfl_xor_sync(0xffffffffu, rsum, off);
            l[ii] = l[ii] * corr + rsum;
#pragma unroll
            for (int dd = 0; dd < 4; dd++) acc[ii][dd] *= corr;
        }
        __syncthreads();

#pragma unroll
        for (int ii = 0; ii < 8; ii++)
#pragma unroll
            for (int jj = 0; jj < 4; jj++)
                KPs[(ty * 8 + ii) * QP + tx + jj * 16] = s[ii][jj];
        __syncthreads();

#pragma unroll 8
        for (int j = 0; j < 64; ++j) {
            float vf[4];
#pragma unroll
            for (int dd = 0; dd < 4; dd++) vf[dd] = Vs[j * VP + tx + dd * 16];
#pragma unroll
            for (int ii = 0; ii < 8; ii++) {
                float pv = KPs[(ty * 8 + ii) * QP + j];
                acc[ii][0] += pv * vf[0];
                acc[ii][1] += pv * vf[1];
                acc[ii][2] += pv * vf[2];
                acc[ii][3] += pv * vf[3];
            }
        }
    }

#pragma unroll
    for (int ii = 0; ii < 8; ii++) {
        float inv = 1.0f / l[ii];
        int row = b * SEQ + qt * 64 + ty * 8 + ii;
        float* o = ctx + (size_t)row * HID + h * 64;
#pragma unroll
        for (int dd = 0; dd < 4; dd++)
            o[tx + dd * 16] = acc[ii][dd] * inv;
    }
}

// ---------------------------------------------------------------------------
// kernel_launch
// ---------------------------------------------------------------------------
extern "C" void kernel_launch(void* const* d_in, const int* in_sizes, int n_in,
                              void* d_out, int out_size)
{
    const float* hidden  = (const float*)d_in[0];
    const float* qkv_w   = (const float*)d_in[2];
    const float* dense_w = (const float*)d_in[3];
    float* out = (float*)d_out;

    float* qkv; cudaGetSymbolAddress((void**)&qkv, g_qkv);
    float* ctx; cudaGetSymbolAddress((void**)&ctx, g_ctx);
    __nv_bfloat16* ah;  cudaGetSymbolAddress((void**)&ah,  g_ah);
    __nv_bfloat16* al;  cudaGetSymbolAddress((void**)&al,  g_al);
    __nv_bfloat16* wth; cudaGetSymbolAddress((void**)&wth, g_wth);
    __nv_bfloat16* wtl; cudaGetSymbolAddress((void**)&wtl, g_wtl);

    cudaFuncSetAttribute(gemm_hmma, cudaFuncAttributeMaxDynamicSharedMemorySize, GSMEM);
    const int attn_smem = (2 * 64 * QP + 64 * VP) * (int)sizeof(float);
    cudaFuncSetAttribute(attn_kernel, cudaFuncAttributeMaxDynamicSharedMemorySize,
                         attn_smem);

    const int nact = ROWS * HID;

    // 1) QKV path
    split_act<<<(nact / 4 + 255) / 256, 256>>>(hidden, ah, al, nact);
    transpose_split<<<dim3(QKVP / 32, HID / 32), dim3(32, 8)>>>(qkv_w, wth, wtl, HID, QKVN);
    gemm_hmma<<<dim3(QKVP / 128, ROWS / 128), 256, GSMEM>>>(
        ah, al, wth, wtl, qkv, QKVP, QKVP);

    // 2) RoPE
    rope_table_kernel<<<(SEQ * 32 + 255) / 256, 256>>>();
    rope_kernel<<<ROWS, 256>>>(qkv);

    // 3) Attention
    attn_kernel<<<dim3(SEQ / 64, NHEAD, 2), 128, attn_smem>>>(qkv, ctx);

    // 4) Dense path
    split_act<<<(nact / 4 + 255) / 256, 256>>>(ctx, ah, al, nact);
    transpose_split<<<dim3(DNP / 32, HID / 32), dim3(32, 8)>>>(dense_w, wth, wtl, HID, HID);
    gemm_hmma<<<dim3(DNP / 128, ROWS / 128), 256, GSMEM>>>(
        ah, al, wth, wtl, out, HID, HID);
}